// round 1
// baseline (speedup 1.0000x reference)
#include <cuda_runtime.h>
#include <math.h>

#define BB   2
#define SEQ  2048
#define DM   1024
#define NH   16
#define DKH  64
#define MTOT (BB*SEQ)   // 4096

// Scratch (allocation-free rule: __device__ globals)
__device__ float g_Q[(size_t)BB*NH*SEQ*DKH];   // [B,H,S,dk]
__device__ float g_K[(size_t)BB*NH*SEQ*DKH];
__device__ float g_V[(size_t)BB*NH*SEQ*DKH];
__device__ float g_AO[(size_t)MTOT*DM];        // [B,S,H*dk] attention output

// ---------------------------------------------------------------------------
// C = A(MxK) * W(NxK)^T.  128x128 tile, BK=8, 256 threads, 8x8 per thread.
// blockIdx.z selects (W,C) pair so QKV is one launch.
// remap==1: scatter into [B,H,S,dk] layout. remap==0: row-major [M,N].
// ---------------------------------------------------------------------------
__global__ void __launch_bounds__(256) gemm128_nt(
    const float* __restrict__ A,
    const float* __restrict__ W0, const float* __restrict__ W1, const float* __restrict__ W2,
    float* __restrict__ C0, float* __restrict__ C1, float* __restrict__ C2,
    int Kdim, int Ndim, int remap)
{
    const float* W = (blockIdx.z == 0) ? W0 : (blockIdx.z == 1 ? W1 : W2);
    float*       C = (blockIdx.z == 0) ? C0 : (blockIdx.z == 1 ? C1 : C2);

    __shared__ __align__(16) float As[8][132];
    __shared__ __align__(16) float Bs[8][132];

    const int tid = threadIdx.x;
    const int bm = blockIdx.y * 128;
    const int bn = blockIdx.x * 128;
    const int lr = tid >> 1;          // 0..127
    const int lk = (tid & 1) * 4;     // 0 or 4
    const float* Ap = A + (size_t)(bm + lr) * Kdim + lk;
    const float* Wp = W + (size_t)(bn + lr) * Kdim + lk;

    const int ty = tid >> 4;          // 0..15
    const int tx = tid & 15;          // 0..15

    float acc[8][8];
#pragma unroll
    for (int i = 0; i < 8; i++)
#pragma unroll
        for (int j = 0; j < 8; j++) acc[i][j] = 0.0f;

    for (int k0 = 0; k0 < Kdim; k0 += 8) {
        float4 av = *(const float4*)(Ap + k0);
        float4 bv = *(const float4*)(Wp + k0);
        __syncthreads();
        As[lk+0][lr] = av.x; As[lk+1][lr] = av.y; As[lk+2][lr] = av.z; As[lk+3][lr] = av.w;
        Bs[lk+0][lr] = bv.x; Bs[lk+1][lr] = bv.y; Bs[lk+2][lr] = bv.z; Bs[lk+3][lr] = bv.w;
        __syncthreads();
#pragma unroll
        for (int kk = 0; kk < 8; kk++) {
            float4 a0 = *(const float4*)&As[kk][ty*8];
            float4 a1 = *(const float4*)&As[kk][ty*8+4];
            float4 b0 = *(const float4*)&Bs[kk][tx*8];
            float4 b1 = *(const float4*)&Bs[kk][tx*8+4];
            float a[8] = {a0.x,a0.y,a0.z,a0.w,a1.x,a1.y,a1.z,a1.w};
            float b[8] = {b0.x,b0.y,b0.z,b0.w,b1.x,b1.y,b1.z,b1.w};
#pragma unroll
            for (int i = 0; i < 8; i++)
#pragma unroll
                for (int j = 0; j < 8; j++)
                    acc[i][j] = fmaf(a[i], b[j], acc[i][j]);
        }
    }

    if (remap) {
        // write into [B,H,S,dk]: row m -> (b=m>>11, s=m&2047), col n -> (h=n>>6, d=n&63)
#pragma unroll
        for (int i = 0; i < 8; i++) {
            int row = bm + ty*8 + i;
            int b = row >> 11, s = row & (SEQ-1);
#pragma unroll
            for (int j = 0; j < 8; j++) {
                int col = bn + tx*8 + j;
                int h = col >> 6, d = col & (DKH-1);
                size_t idx = (((size_t)(b*NH + h) * SEQ) + s) * DKH + d;
                C[idx] = acc[i][j];
            }
        }
    } else {
#pragma unroll
        for (int i = 0; i < 8; i++) {
            int row = bm + ty*8 + i;
            float* cp = C + (size_t)row * Ndim + bn + tx*8;
            *(float4*)(cp+0) = make_float4(acc[i][0], acc[i][1], acc[i][2], acc[i][3]);
            *(float4*)(cp+4) = make_float4(acc[i][4], acc[i][5], acc[i][6], acc[i][7]);
        }
    }
}

// ---------------------------------------------------------------------------
// Causal flash attention, fp32. Block = 64 query rows; loops key tiles of 64.
// 256 threads as 16x16; each computes a 4x4 micro-tile of the 64x64 score
// tile (rows ty*4+i, cols tx*4+j) and a 4x4 tile of the output (dims tx*4+j).
// KP buffer holds K-transposed during QK^T, then is reused to hold P.
// Shared = 3 * 16KB = 48KB exactly.
// ---------------------------------------------------------------------------
__global__ void __launch_bounds__(256) attn64(
    const float* __restrict__ Qg, const float* __restrict__ Kg,
    const float* __restrict__ Vg, float* __restrict__ AO)
{
    const int qt = blockIdx.x;            // query tile 0..31
    const int bh = blockIdx.y;            // 0..31
    const int b  = bh >> 4;
    const int h  = bh & (NH-1);
    const float* Qb = Qg + (size_t)bh * SEQ * DKH;
    const float* Kb = Kg + (size_t)bh * SEQ * DKH;
    const float* Vb = Vg + (size_t)bh * SEQ * DKH;

    __shared__ __align__(16) float Qs[DKH][64];   // [d][r], prescaled by 1/sqrt(dk)
    __shared__ __align__(16) float KP[64][64];    // Kt [d][c], reused as P [r][c]
    __shared__ __align__(16) float Vs[64][64];    // [c][d]

    const int tid = threadIdx.x;
    const int ty = tid >> 4, tx = tid & 15;
    const int lrr = tid >> 2;             // 0..63 (load row)
    const int ld4 = (tid & 3) * 4;        // load d-quad base

    // Load Q tile transposed + prescale
    {
        const float* qp = Qb + (size_t)(qt*64 + lrr) * DKH;
#pragma unroll
        for (int i = 0; i < 4; i++) {
            int d0 = ld4 + i*16;
            float4 v = *(const float4*)(qp + d0);
            Qs[d0+0][lrr] = v.x * 0.125f;
            Qs[d0+1][lrr] = v.y * 0.125f;
            Qs[d0+2][lrr] = v.z * 0.125f;
            Qs[d0+3][lrr] = v.w * 0.125f;
        }
    }

    float m[4], l[4], o[4][4];
#pragma unroll
    for (int i = 0; i < 4; i++) {
        m[i] = -INFINITY; l[i] = 0.0f;
#pragma unroll
        for (int j = 0; j < 4; j++) o[i][j] = 0.0f;
    }

    for (int kt = 0; kt <= qt; kt++) {
        __syncthreads();   // previous iteration fully consumed KP/Vs
        {
            const float* kp = Kb + (size_t)(kt*64 + lrr) * DKH;
            const float* vp = Vb + (size_t)(kt*64 + lrr) * DKH;
#pragma unroll
            for (int i = 0; i < 4; i++) {
                int d0 = ld4 + i*16;
                float4 kv = *(const float4*)(kp + d0);
                KP[d0+0][lrr] = kv.x;
                KP[d0+1][lrr] = kv.y;
                KP[d0+2][lrr] = kv.z;
                KP[d0+3][lrr] = kv.w;
                float4 vv = *(const float4*)(vp + d0);
                *(float4*)&Vs[lrr][d0] = vv;
            }
        }
        __syncthreads();

        // S = (Q*scale) K^T : 4x4 micro-tile
        float s[4][4];
#pragma unroll
        for (int i = 0; i < 4; i++)
#pragma unroll
            for (int j = 0; j < 4; j++) s[i][j] = 0.0f;
#pragma unroll 16
        for (int d = 0; d < DKH; d++) {
            float4 a  = *(const float4*)&Qs[d][ty*4];
            float4 bb = *(const float4*)&KP[d][tx*4];
            float av[4] = {a.x, a.y, a.z, a.w};
            float bv[4] = {bb.x, bb.y, bb.z, bb.w};
#pragma unroll
            for (int i = 0; i < 4; i++)
#pragma unroll
                for (int j = 0; j < 4; j++)
                    s[i][j] = fmaf(av[i], bv[j], s[i][j]);
        }

        if (kt == qt) {   // causal mask on the diagonal tile (local indices)
#pragma unroll
            for (int i = 0; i < 4; i++)
#pragma unroll
                for (int j = 0; j < 4; j++)
                    if (tx*4 + j > ty*4 + i) s[i][j] = -INFINITY;
        }

        // Online softmax per row (16 lanes of same ty share a row group)
#pragma unroll
        for (int i = 0; i < 4; i++) {
            float mx = fmaxf(fmaxf(s[i][0], s[i][1]), fmaxf(s[i][2], s[i][3]));
#pragma unroll
            for (int off = 1; off < 16; off <<= 1)
                mx = fmaxf(mx, __shfl_xor_sync(0xffffffffu, mx, off));
            float mn = fmaxf(m[i], mx);
            float alpha = __expf(m[i] - mn);
            m[i] = mn;
            float ls = 0.0f;
#pragma unroll
            for (int j = 0; j < 4; j++) {
                s[i][j] = __expf(s[i][j] - mn);
                ls += s[i][j];
            }
#pragma unroll
            for (int off = 1; off < 16; off <<= 1)
                ls += __shfl_xor_sync(0xffffffffu, ls, off);
            l[i] = l[i] * alpha + ls;
#pragma unroll
            for (int j = 0; j < 4; j++) o[i][j] *= alpha;
        }

        __syncthreads();   // all lanes done reading KP as K-transposed
#pragma unroll
        for (int i = 0; i < 4; i++)
            *(float4*)&KP[ty*4+i][tx*4] = make_float4(s[i][0], s[i][1], s[i][2], s[i][3]);
        __syncthreads();

        // O += P V  (each thread: rows ty*4+i, output dims tx*4+j)
#pragma unroll 16
        for (int c = 0; c < 64; c++) {
            float4 v = *(const float4*)&Vs[c][tx*4];
            float p0 = KP[ty*4+0][c];
            float p1 = KP[ty*4+1][c];
            float p2 = KP[ty*4+2][c];
            float p3 = KP[ty*4+3][c];
            o[0][0] = fmaf(p0, v.x, o[0][0]); o[0][1] = fmaf(p0, v.y, o[0][1]);
            o[0][2] = fmaf(p0, v.z, o[0][2]); o[0][3] = fmaf(p0, v.w, o[0][3]);
            o[1][0] = fmaf(p1, v.x, o[1][0]); o[1][1] = fmaf(p1, v.y, o[1][1]);
            o[1][2] = fmaf(p1, v.z, o[1][2]); o[1][3] = fmaf(p1, v.w, o[1][3]);
            o[2][0] = fmaf(p2, v.x, o[2][0]); o[2][1] = fmaf(p2, v.y, o[2][1]);
            o[2][2] = fmaf(p2, v.z, o[2][2]); o[2][3] = fmaf(p2, v.w, o[2][3]);
            o[3][0] = fmaf(p3, v.x, o[3][0]); o[3][1] = fmaf(p3, v.y, o[3][1]);
            o[3][2] = fmaf(p3, v.z, o[3][2]); o[3][3] = fmaf(p3, v.w, o[3][3]);
        }
    }

    // Write normalized output into [B,S,H*dk]
#pragma unroll
    for (int i = 0; i < 4; i++) {
        int qg = qt*64 + ty*4 + i;
        float inv = 1.0f / l[i];
        float* op = AO + ((size_t)(b*SEQ + qg) * DM) + h*DKH + tx*4;
        *(float4*)op = make_float4(o[i][0]*inv, o[i][1]*inv, o[i][2]*inv, o[i][3]*inv);
    }
}

// ---------------------------------------------------------------------------
extern "C" void kernel_launch(void* const* d_in, const int* in_sizes, int n_in,
                              void* d_out, int out_size)
{
    const float* x  = (const float*)d_in[0];
    const float* wq = (const float*)d_in[1];
    const float* wk = (const float*)d_in[2];
    const float* wv = (const float*)d_in[3];
    const float* wo = (const float*)d_in[4];

    float *Qp, *Kp, *Vp, *AOp;
    cudaGetSymbolAddress((void**)&Qp,  g_Q);
    cudaGetSymbolAddress((void**)&Kp,  g_K);
    cudaGetSymbolAddress((void**)&Vp,  g_V);
    cudaGetSymbolAddress((void**)&AOp, g_AO);

    // QKV projections (one launch, z selects weight/output)
    dim3 g1(DM/128, MTOT/128, 3);
    gemm128_nt<<<g1, 256>>>(x, wq, wk, wv, Qp, Kp, Vp, DM, DM, 1);

    // Causal attention
    dim3 g2(SEQ/64, BB*NH, 1);
    attn64<<<g2, 256>>>(Qp, Kp, Vp, AOp);

    // Output projection -> d_out
    dim3 g3(DM/128, MTOT/128, 1);
    gemm128_nt<<<g3, 256>>>(AOp, wo, wo, wo,
                            (float*)d_out, (float*)d_out, (float*)d_out, DM, DM, 0);
}

// round 3
// speedup vs baseline: 1.6401x; 1.6401x over previous
#include <cuda_runtime.h>
#include <math.h>
#include <cstdint>

#define BB   2
#define SEQ  2048
#define DM   1024
#define NH   16
#define DKH  64
#define MTOT (BB*SEQ)   // 4096

// Scratch (allocation-free rule: __device__ globals)
__device__ float g_Q[(size_t)BB*NH*SEQ*DKH];   // [B,H,S,dk]
__device__ float g_K[(size_t)BB*NH*SEQ*DKH];
__device__ float g_V[(size_t)BB*NH*SEQ*DKH];
__device__ float g_AO[(size_t)MTOT*DM];        // [B,S,H*dk]

// ---------------------------------------------------------------------------
// helpers (plain PTX ISA only — compute_100 has no tcgen05)
// ---------------------------------------------------------------------------
__device__ __forceinline__ uint32_t smem_u32(const void* p) {
    uint32_t a;
    asm("{ .reg .u64 t; cvta.to.shared.u64 t, %1; cvt.u32.u64 %0, t; }" : "=r"(a) : "l"(p));
    return a;
}
__device__ __forceinline__ void cp16(uint32_t dst, const void* src) {
    asm volatile("cp.async.cg.shared.global [%0], [%1], 16;" :: "r"(dst), "l"(src));
}
__device__ __forceinline__ uint32_t f2tf(float f) {
    uint32_t r;
    asm("cvt.rna.tf32.f32 %0, %1;" : "=r"(r) : "f"(f));
    return r;
}
__device__ __forceinline__ void mma_tf32(float c[4],
    uint32_t a0, uint32_t a1, uint32_t a2, uint32_t a3, uint32_t b0, uint32_t b1) {
    asm volatile(
        "mma.sync.aligned.m16n8k8.row.col.f32.tf32.tf32.f32 "
        "{%0,%1,%2,%3}, {%4,%5,%6,%7}, {%8,%9}, {%0,%1,%2,%3};"
        : "+f"(c[0]), "+f"(c[1]), "+f"(c[2]), "+f"(c[3])
        : "r"(a0), "r"(a1), "r"(a2), "r"(a3), "r"(b0), "r"(b1));
}

// ---------------------------------------------------------------------------
// tf32 mma.sync GEMM: C(128x128/CTA) = A[M,K=1024] * W[N,K]^T
// 8 warps (2x4), 64x32 per warp, BK=16, 3-stage cp.async pipeline.
// remap=1: scatter into [B,H,S,dk]. remap=0: row-major [M,DM].
// ---------------------------------------------------------------------------
#define BK      16
#define PITCH   20                    // floats per smem row (conflict-free)
#define GSTAGES 3
#define STG_FL  (2*128*PITCH)         // floats per stage (A+B)
#define GSMEM_B (GSTAGES*STG_FL*4)    // 61440 bytes
#define KTILES  (DM/BK)               // 64

__global__ void __launch_bounds__(256) mma_gemm(
    const float* __restrict__ A,
    const float* __restrict__ W0, const float* __restrict__ W1, const float* __restrict__ W2,
    float* __restrict__ C0, float* __restrict__ C1, float* __restrict__ C2,
    int remap)
{
    extern __shared__ __align__(16) float sm[];
    const uint32_t sb = smem_u32(sm);

    const int tid  = threadIdx.x;
    const int wid  = tid >> 5, lane = tid & 31;
    const int wm   = wid >> 2, wn = wid & 3;       // warp 2x4
    const int lg   = lane >> 2;                    // 0..7
    const int lk   = lane & 3;                     // 0..3

    const float* W = (blockIdx.z == 0) ? W0 : (blockIdx.z == 1 ? W1 : W2);
    float*       C = (blockIdx.z == 0) ? C0 : (blockIdx.z == 1 ? C1 : C2);
    const int bm = blockIdx.y * 128;
    const int bn = blockIdx.x * 128;

    float acc[4][4][4];
#pragma unroll
    for (int i = 0; i < 4; i++)
#pragma unroll
        for (int j = 0; j < 4; j++)
#pragma unroll
            for (int k = 0; k < 4; k++) acc[i][j][k] = 0.0f;

    // global->smem: thread covers rows lrow, lrow+64; one 16B quad each
    const int lrow = tid >> 2;            // 0..63
    const int lq   = (tid & 3) * 4;       // float offset 0,4,8,12

#define LOAD_STAGE(kt, s) do { \
        uint32_t _as = sb + (uint32_t)((s)*STG_FL)*4u; \
        uint32_t _bs = _as + (uint32_t)(128*PITCH)*4u; \
        const float* _ap = A + (size_t)(bm + lrow) * DM + (kt)*BK + lq; \
        const float* _wp = W + (size_t)(bn + lrow) * DM + (kt)*BK + lq; \
        cp16(_as + (uint32_t)(lrow*PITCH + lq)*4u, _ap); \
        cp16(_bs + (uint32_t)(lrow*PITCH + lq)*4u, _wp); \
        cp16(_as + (uint32_t)((lrow+64)*PITCH + lq)*4u, _ap + (size_t)64*DM); \
        cp16(_bs + (uint32_t)((lrow+64)*PITCH + lq)*4u, _wp + (size_t)64*DM); \
    } while (0)

#define SA(s, r, k) sm[(s)*STG_FL + (r)*PITCH + (k)]
#define SB_(s, r, k) sm[(s)*STG_FL + 128*PITCH + (r)*PITCH + (k)]

    // prologue
#pragma unroll
    for (int s = 0; s < GSTAGES-1; s++) {
        LOAD_STAGE(s, s);
        asm volatile("cp.async.commit_group;" ::: "memory");
    }

    for (int kt = 0; kt < KTILES; kt++) {
        asm volatile("cp.async.wait_group %0;" :: "n"(GSTAGES-2) : "memory");
        __syncthreads();

        int knext = kt + GSTAGES - 1;
        if (knext < KTILES) LOAD_STAGE(knext, knext % GSTAGES);
        asm volatile("cp.async.commit_group;" ::: "memory");

        const int s = kt % GSTAGES;
#pragma unroll
        for (int k0 = 0; k0 < BK; k0 += 8) {
            const int kr = k0 + lk;
            uint32_t af[4][4], bf[4][2];
#pragma unroll
            for (int tm = 0; tm < 4; tm++) {
                int r = wm*64 + tm*16 + lg;
                af[tm][0] = f2tf(SA(s, r,   kr));
                af[tm][1] = f2tf(SA(s, r+8, kr));
                af[tm][2] = f2tf(SA(s, r,   kr+4));
                af[tm][3] = f2tf(SA(s, r+8, kr+4));
            }
#pragma unroll
            for (int tn = 0; tn < 4; tn++) {
                int c = wn*32 + tn*8 + lg;
                bf[tn][0] = f2tf(SB_(s, c, kr));
                bf[tn][1] = f2tf(SB_(s, c, kr+4));
            }
#pragma unroll
            for (int tm = 0; tm < 4; tm++)
#pragma unroll
                for (int tn = 0; tn < 4; tn++)
                    mma_tf32(acc[tm][tn], af[tm][0], af[tm][1], af[tm][2], af[tm][3],
                             bf[tn][0], bf[tn][1]);
        }
        __syncthreads();
    }

    // epilogue
#pragma unroll
    for (int tm = 0; tm < 4; tm++) {
        int r0 = bm + wm*64 + tm*16 + lg;
        int r1 = r0 + 8;
#pragma unroll
        for (int tn = 0; tn < 4; tn++) {
            int c0 = bn + wn*32 + tn*8 + 2*lk;
            if (remap) {
                int b0v = r0 >> 11, s0 = r0 & (SEQ-1);
                int b1v = r1 >> 11, s1 = r1 & (SEQ-1);
                int h = c0 >> 6, d = c0 & (DKH-1);
                float* p0 = C + (((size_t)(b0v*NH + h) * SEQ) + s0) * DKH + d;
                float* p1 = C + (((size_t)(b1v*NH + h) * SEQ) + s1) * DKH + d;
                *(float2*)p0 = make_float2(acc[tm][tn][0], acc[tm][tn][1]);
                *(float2*)p1 = make_float2(acc[tm][tn][2], acc[tm][tn][3]);
            } else {
                float* p0 = C + (size_t)r0 * DM + c0;
                float* p1 = C + (size_t)r1 * DM + c0;
                *(float2*)p0 = make_float2(acc[tm][tn][0], acc[tm][tn][1]);
                *(float2*)p1 = make_float2(acc[tm][tn][2], acc[tm][tn][3]);
            }
        }
    }
#undef LOAD_STAGE
#undef SA
#undef SB_
}

// ---------------------------------------------------------------------------
// Causal flash attention, fp32 SIMT (unchanged — passing since round 1)
// ---------------------------------------------------------------------------
__global__ void __launch_bounds__(256) attn64(
    const float* __restrict__ Qg, const float* __restrict__ Kg,
    const float* __restrict__ Vg, float* __restrict__ AO)
{
    const int qt = blockIdx.x;
    const int bh = blockIdx.y;
    const int b  = bh >> 4;
    const int h  = bh & (NH-1);
    const float* Qb = Qg + (size_t)bh * SEQ * DKH;
    const float* Kb = Kg + (size_t)bh * SEQ * DKH;
    const float* Vb = Vg + (size_t)bh * SEQ * DKH;

    __shared__ __align__(16) float Qs[DKH][64];
    __shared__ __align__(16) float KP[64][64];
    __shared__ __align__(16) float Vs[64][64];

    const int tid = threadIdx.x;
    const int ty = tid >> 4, tx = tid & 15;
    const int lrr = tid >> 2;
    const int ld4 = (tid & 3) * 4;

    {
        const float* qp = Qb + (size_t)(qt*64 + lrr) * DKH;
#pragma unroll
        for (int i = 0; i < 4; i++) {
            int d0 = ld4 + i*16;
            float4 v = *(const float4*)(qp + d0);
            Qs[d0+0][lrr] = v.x * 0.125f;
            Qs[d0+1][lrr] = v.y * 0.125f;
            Qs[d0+2][lrr] = v.z * 0.125f;
            Qs[d0+3][lrr] = v.w * 0.125f;
        }
    }

    float m[4], l[4], o[4][4];
#pragma unroll
    for (int i = 0; i < 4; i++) {
        m[i] = -INFINITY; l[i] = 0.0f;
#pragma unroll
        for (int j = 0; j < 4; j++) o[i][j] = 0.0f;
    }

    for (int kt = 0; kt <= qt; kt++) {
        __syncthreads();
        {
            const float* kp = Kb + (size_t)(kt*64 + lrr) * DKH;
            const float* vp = Vb + (size_t)(kt*64 + lrr) * DKH;
#pragma unroll
            for (int i = 0; i < 4; i++) {
                int d0 = ld4 + i*16;
                float4 kv = *(const float4*)(kp + d0);
                KP[d0+0][lrr] = kv.x;
                KP[d0+1][lrr] = kv.y;
                KP[d0+2][lrr] = kv.z;
                KP[d0+3][lrr] = kv.w;
                float4 vv = *(const float4*)(vp + d0);
                *(float4*)&Vs[lrr][d0] = vv;
            }
        }
        __syncthreads();

        float s[4][4];
#pragma unroll
        for (int i = 0; i < 4; i++)
#pragma unroll
            for (int j = 0; j < 4; j++) s[i][j] = 0.0f;
#pragma unroll 16
        for (int d = 0; d < DKH; d++) {
            float4 a  = *(const float4*)&Qs[d][ty*4];
            float4 bb = *(const float4*)&KP[d][tx*4];
            float av[4] = {a.x, a.y, a.z, a.w};
            float bv[4] = {bb.x, bb.y, bb.z, bb.w};
#pragma unroll
            for (int i = 0; i < 4; i++)
#pragma unroll
                for (int j = 0; j < 4; j++)
                    s[i][j] = fmaf(av[i], bv[j], s[i][j]);
        }

        if (kt == qt) {
#pragma unroll
            for (int i = 0; i < 4; i++)
#pragma unroll
                for (int j = 0; j < 4; j++)
                    if (tx*4 + j > ty*4 + i) s[i][j] = -INFINITY;
        }

#pragma unroll
        for (int i = 0; i < 4; i++) {
            float mx = fmaxf(fmaxf(s[i][0], s[i][1]), fmaxf(s[i][2], s[i][3]));
#pragma unroll
            for (int off = 1; off < 16; off <<= 1)
                mx = fmaxf(mx, __shfl_xor_sync(0xffffffffu, mx, off));
            float mn = fmaxf(m[i], mx);
            float alpha = __expf(m[i] - mn);
            m[i] = mn;
            float ls = 0.0f;
#pragma unroll
            for (int j = 0; j < 4; j++) {
                s[i][j] = __expf(s[i][j] - mn);
                ls += s[i][j];
            }
#pragma unroll
            for (int off = 1; off < 16; off <<= 1)
                ls += __shfl_xor_sync(0xffffffffu, ls, off);
            l[i] = l[i] * alpha + ls;
#pragma unroll
            for (int j = 0; j < 4; j++) o[i][j] *= alpha;
        }

        __syncthreads();
#pragma unroll
        for (int i = 0; i < 4; i++)
            *(float4*)&KP[ty*4+i][tx*4] = make_float4(s[i][0], s[i][1], s[i][2], s[i][3]);
        __syncthreads();

#pragma unroll 16
        for (int c = 0; c < 64; c++) {
            float4 v = *(const float4*)&Vs[c][tx*4];
            float p0 = KP[ty*4+0][c];
            float p1 = KP[ty*4+1][c];
            float p2 = KP[ty*4+2][c];
            float p3 = KP[ty*4+3][c];
            o[0][0] = fmaf(p0, v.x, o[0][0]); o[0][1] = fmaf(p0, v.y, o[0][1]);
            o[0][2] = fmaf(p0, v.z, o[0][2]); o[0][3] = fmaf(p0, v.w, o[0][3]);
            o[1][0] = fmaf(p1, v.x, o[1][0]); o[1][1] = fmaf(p1, v.y, o[1][1]);
            o[1][2] = fmaf(p1, v.z, o[1][2]); o[1][3] = fmaf(p1, v.w, o[1][3]);
            o[2][0] = fmaf(p2, v.x, o[2][0]); o[2][1] = fmaf(p2, v.y, o[2][1]);
            o[2][2] = fmaf(p2, v.z, o[2][2]); o[2][3] = fmaf(p2, v.w, o[2][3]);
            o[3][0] = fmaf(p3, v.x, o[3][0]); o[3][1] = fmaf(p3, v.y, o[3][1]);
            o[3][2] = fmaf(p3, v.z, o[3][2]); o[3][3] = fmaf(p3, v.w, o[3][3]);
        }
    }

#pragma unroll
    for (int i = 0; i < 4; i++) {
        int qg = qt*64 + ty*4 + i;
        float inv = 1.0f / l[i];
        float* op = AO + ((size_t)(b*SEQ + qg) * DM) + h*DKH + tx*4;
        *(float4*)op = make_float4(o[i][0]*inv, o[i][1]*inv, o[i][2]*inv, o[i][3]*inv);
    }
}

// ---------------------------------------------------------------------------
extern "C" void kernel_launch(void* const* d_in, const int* in_sizes, int n_in,
                              void* d_out, int out_size)
{
    const float* x  = (const float*)d_in[0];
    const float* wq = (const float*)d_in[1];
    const float* wk = (const float*)d_in[2];
    const float* wv = (const float*)d_in[3];
    const float* wo = (const float*)d_in[4];

    float *Qp, *Kp, *Vp, *AOp;
    cudaGetSymbolAddress((void**)&Qp,  g_Q);
    cudaGetSymbolAddress((void**)&Kp,  g_K);
    cudaGetSymbolAddress((void**)&Vp,  g_V);
    cudaGetSymbolAddress((void**)&AOp, g_AO);

    static int smem_set = 0;
    if (!smem_set) {
        cudaFuncSetAttribute(mma_gemm, cudaFuncAttributeMaxDynamicSharedMemorySize, GSMEM_B);
        smem_set = 1;
    }

    // QKV projections (tf32 mma.sync), scatter to [B,H,S,dk]
    dim3 g1(DM/128, MTOT/128, 3);
    mma_gemm<<<g1, 256, GSMEM_B>>>(x, wq, wk, wv, Qp, Kp, Vp, 1);

    // Causal attention (fp32 SIMT)
    dim3 g2(SEQ/64, BB*NH, 1);
    attn64<<<g2, 256>>>(Qp, Kp, Vp, AOp);

    // Output projection (tf32 mma.sync) -> d_out
    dim3 g3(DM/128, MTOT/128, 1);
    mma_gemm<<<g3, 256, GSMEM_B>>>(AOp, wo, wo, wo,
                                   (float*)d_out, (float*)d_out, (float*)d_out, 0);
}

// round 4
// speedup vs baseline: 2.4608x; 1.5004x over previous
#include <cuda_runtime.h>
#include <math.h>
#include <cstdint>

#define BB   2
#define SEQ  2048
#define DM   1024
#define NH   16
#define DKH  64
#define MTOT (BB*SEQ)   // 4096

// Scratch (allocation-free rule: __device__ globals)
__device__ float g_Q[(size_t)BB*NH*SEQ*DKH];   // [B,H,S,dk]
__device__ float g_K[(size_t)BB*NH*SEQ*DKH];
__device__ float g_V[(size_t)BB*NH*SEQ*DKH];
__device__ float g_AO[(size_t)MTOT*DM];        // [B,S,H*dk]

// ---------------------------------------------------------------------------
// helpers (plain PTX ISA only — compute_100 has no tcgen05)
// ---------------------------------------------------------------------------
__device__ __forceinline__ uint32_t smem_u32(const void* p) {
    uint32_t a;
    asm("{ .reg .u64 t; cvta.to.shared.u64 t, %1; cvt.u32.u64 %0, t; }" : "=r"(a) : "l"(p));
    return a;
}
__device__ __forceinline__ void cp16(uint32_t dst, const void* src) {
    asm volatile("cp.async.cg.shared.global [%0], [%1], 16;" :: "r"(dst), "l"(src));
}
__device__ __forceinline__ uint32_t f2tf(float f) {
    uint32_t r;
    asm("cvt.rna.tf32.f32 %0, %1;" : "=r"(r) : "f"(f));
    return r;
}
__device__ __forceinline__ void mma_tf32(float c[4],
    uint32_t a0, uint32_t a1, uint32_t a2, uint32_t a3, uint32_t b0, uint32_t b1) {
    asm volatile(
        "mma.sync.aligned.m16n8k8.row.col.f32.tf32.tf32.f32 "
        "{%0,%1,%2,%3}, {%4,%5,%6,%7}, {%8,%9}, {%0,%1,%2,%3};"
        : "+f"(c[0]), "+f"(c[1]), "+f"(c[2]), "+f"(c[3])
        : "r"(a0), "r"(a1), "r"(a2), "r"(a3), "r"(b0), "r"(b1));
}

// ---------------------------------------------------------------------------
// tf32 mma.sync GEMM (unchanged from round 3): C(128x128/CTA) = A * W^T
// ---------------------------------------------------------------------------
#define BK      16
#define PITCH   20
#define GSTAGES 3
#define STG_FL  (2*128*PITCH)
#define GSMEM_B (GSTAGES*STG_FL*4)
#define KTILES  (DM/BK)

__global__ void __launch_bounds__(256) mma_gemm(
    const float* __restrict__ A,
    const float* __restrict__ W0, const float* __restrict__ W1, const float* __restrict__ W2,
    float* __restrict__ C0, float* __restrict__ C1, float* __restrict__ C2,
    int remap)
{
    extern __shared__ __align__(16) float sm[];
    const uint32_t sb = smem_u32(sm);

    const int tid  = threadIdx.x;
    const int wid  = tid >> 5, lane = tid & 31;
    const int wm   = wid >> 2, wn = wid & 3;
    const int lg   = lane >> 2;
    const int lk   = lane & 3;

    const float* W = (blockIdx.z == 0) ? W0 : (blockIdx.z == 1 ? W1 : W2);
    float*       C = (blockIdx.z == 0) ? C0 : (blockIdx.z == 1 ? C1 : C2);
    const int bm = blockIdx.y * 128;
    const int bn = blockIdx.x * 128;

    float acc[4][4][4];
#pragma unroll
    for (int i = 0; i < 4; i++)
#pragma unroll
        for (int j = 0; j < 4; j++)
#pragma unroll
            for (int k = 0; k < 4; k++) acc[i][j][k] = 0.0f;

    const int lrow = tid >> 2;
    const int lq   = (tid & 3) * 4;

#define LOAD_STAGE(kt, s) do { \
        uint32_t _as = sb + (uint32_t)((s)*STG_FL)*4u; \
        uint32_t _bs = _as + (uint32_t)(128*PITCH)*4u; \
        const float* _ap = A + (size_t)(bm + lrow) * DM + (kt)*BK + lq; \
        const float* _wp = W + (size_t)(bn + lrow) * DM + (kt)*BK + lq; \
        cp16(_as + (uint32_t)(lrow*PITCH + lq)*4u, _ap); \
        cp16(_bs + (uint32_t)(lrow*PITCH + lq)*4u, _wp); \
        cp16(_as + (uint32_t)((lrow+64)*PITCH + lq)*4u, _ap + (size_t)64*DM); \
        cp16(_bs + (uint32_t)((lrow+64)*PITCH + lq)*4u, _wp + (size_t)64*DM); \
    } while (0)

#define SA(s, r, k) sm[(s)*STG_FL + (r)*PITCH + (k)]
#define SB_(s, r, k) sm[(s)*STG_FL + 128*PITCH + (r)*PITCH + (k)]

#pragma unroll
    for (int s = 0; s < GSTAGES-1; s++) {
        LOAD_STAGE(s, s);
        asm volatile("cp.async.commit_group;" ::: "memory");
    }

    for (int kt = 0; kt < KTILES; kt++) {
        asm volatile("cp.async.wait_group %0;" :: "n"(GSTAGES-2) : "memory");
        __syncthreads();

        int knext = kt + GSTAGES - 1;
        if (knext < KTILES) LOAD_STAGE(knext, knext % GSTAGES);
        asm volatile("cp.async.commit_group;" ::: "memory");

        const int s = kt % GSTAGES;
#pragma unroll
        for (int k0 = 0; k0 < BK; k0 += 8) {
            const int kr = k0 + lk;
            uint32_t af[4][4], bf[4][2];
#pragma unroll
            for (int tm = 0; tm < 4; tm++) {
                int r = wm*64 + tm*16 + lg;
                af[tm][0] = f2tf(SA(s, r,   kr));
                af[tm][1] = f2tf(SA(s, r+8, kr));
                af[tm][2] = f2tf(SA(s, r,   kr+4));
                af[tm][3] = f2tf(SA(s, r+8, kr+4));
            }
#pragma unroll
            for (int tn = 0; tn < 4; tn++) {
                int c = wn*32 + tn*8 + lg;
                bf[tn][0] = f2tf(SB_(s, c, kr));
                bf[tn][1] = f2tf(SB_(s, c, kr+4));
            }
#pragma unroll
            for (int tm = 0; tm < 4; tm++)
#pragma unroll
                for (int tn = 0; tn < 4; tn++)
                    mma_tf32(acc[tm][tn], af[tm][0], af[tm][1], af[tm][2], af[tm][3],
                             bf[tn][0], bf[tn][1]);
        }
        __syncthreads();
    }

#pragma unroll
    for (int tm = 0; tm < 4; tm++) {
        int r0 = bm + wm*64 + tm*16 + lg;
        int r1 = r0 + 8;
#pragma unroll
        for (int tn = 0; tn < 4; tn++) {
            int c0 = bn + wn*32 + tn*8 + 2*lk;
            if (remap) {
                int b0v = r0 >> 11, s0 = r0 & (SEQ-1);
                int b1v = r1 >> 11, s1 = r1 & (SEQ-1);
                int h = c0 >> 6, d = c0 & (DKH-1);
                float* p0 = C + (((size_t)(b0v*NH + h) * SEQ) + s0) * DKH + d;
                float* p1 = C + (((size_t)(b1v*NH + h) * SEQ) + s1) * DKH + d;
                *(float2*)p0 = make_float2(acc[tm][tn][0], acc[tm][tn][1]);
                *(float2*)p1 = make_float2(acc[tm][tn][2], acc[tm][tn][3]);
            } else {
                float* p0 = C + (size_t)r0 * DM + c0;
                float* p1 = C + (size_t)r1 * DM + c0;
                *(float2*)p0 = make_float2(acc[tm][tn][0], acc[tm][tn][1]);
                *(float2*)p1 = make_float2(acc[tm][tn][2], acc[tm][tn][3]);
            }
        }
    }
#undef LOAD_STAGE
#undef SA
#undef SB_
}

// ---------------------------------------------------------------------------
// Causal flash attention on tf32 mma.sync.
// CTA: 128 q-rows x one (b,h). 8 warps x 16 rows, full 64-key tiles.
// K-slot remap: mma slots (lk, lk+4) hold columns (2lk, 2lk+1) on both A and B
// (k-sum is order-independent) -> float2 fragment loads.
// ---------------------------------------------------------------------------
#define QT      128
#define KT      64
#define APITCH  68
#define QS_OFF  0
#define KS_OFF  (QT*APITCH)                    // 8704
#define VS_OFF  (KS_OFF + 2*KT*APITCH)         // 17408
#define PS_OFF  (VS_OFF + 2*KT*APITCH)         // 26112
#define ASMEM_B ((PS_OFF + QT*APITCH)*4)       // 139264 bytes

__global__ void __launch_bounds__(256) attn_mma(
    const float* __restrict__ Qg, const float* __restrict__ Kg,
    const float* __restrict__ Vg, float* __restrict__ AO)
{
    extern __shared__ __align__(16) float asmem[];
    const uint32_t sb = smem_u32(asmem);

    const int tid = threadIdx.x;
    const int wid = tid >> 5, lane = tid & 31;
    const int lg = lane >> 2, lk = lane & 3;
    const int qt = gridDim.x - 1 - blockIdx.x;   // big tiles first
    const int bh = blockIdx.y;
    const int b  = bh >> 4, h = bh & (NH-1);
    const float* Qb = Qg + (size_t)bh * SEQ * DKH;
    const float* Kb = Kg + (size_t)bh * SEQ * DKH;
    const float* Vb = Vg + (size_t)bh * SEQ * DKH;

#define QSV(r,c)   asmem[QS_OFF + (r)*APITCH + (c)]
#define KSV(s,r,c) asmem[KS_OFF + (s)*KT*APITCH + (r)*APITCH + (c)]
#define VSV(s,r,c) asmem[VS_OFF + (s)*KT*APITCH + (r)*APITCH + (c)]
#define PSV(r,c)   asmem[PS_OFF + (r)*APITCH + (c)]

    // load Q tile [128 x 64]
    {
        int row = tid >> 1, cb = (tid & 1) * 32;
        const float* qp = Qb + (size_t)(qt*QT + row) * DKH + cb;
        uint32_t dst = sb + (uint32_t)(QS_OFF + row*APITCH + cb) * 4u;
#pragma unroll
        for (int i = 0; i < 8; i++) cp16(dst + i*16, qp + i*4);
    }

#define LOAD_KV(kt_, s_) do { \
        int _r = tid >> 2, _cb = (tid & 3) * 16; \
        const float* _kp = Kb + (size_t)((kt_)*KT + _r) * DKH + _cb; \
        const float* _vp = Vb + (size_t)((kt_)*KT + _r) * DKH + _cb; \
        uint32_t _kd = sb + (uint32_t)(KS_OFF + (s_)*KT*APITCH + _r*APITCH + _cb) * 4u; \
        uint32_t _vd = sb + (uint32_t)(VS_OFF + (s_)*KT*APITCH + _r*APITCH + _cb) * 4u; \
        _Pragma("unroll") \
        for (int _i = 0; _i < 4; _i++) { \
            cp16(_kd + _i*16, _kp + _i*4); \
            cp16(_vd + _i*16, _vp + _i*4); \
        } } while (0)

    LOAD_KV(0, 0);
    asm volatile("cp.async.commit_group;" ::: "memory");

    float m0 = -INFINITY, m1 = -INFINITY, l0 = 0.0f, l1 = 0.0f;
    float o[8][4];
#pragma unroll
    for (int tn = 0; tn < 8; tn++)
#pragma unroll
        for (int j = 0; j < 4; j++) o[tn][j] = 0.0f;

    const int ntiles = 2*qt + 2;
    const int r0 = qt*QT + wid*16 + lg;   // global row (also r1 = r0+8)
    const int r1 = r0 + 8;
    const float scale = 0.125f;

    for (int kt = 0; kt < ntiles; kt++) {
        const int s = kt & 1;
        if (kt + 1 < ntiles) LOAD_KV(kt + 1, s ^ 1);
        asm volatile("cp.async.commit_group;" ::: "memory");
        asm volatile("cp.async.wait_group 1;" ::: "memory");
        __syncthreads();

        const bool active = (kt*KT <= qt*QT + wid*16 + 15);
        if (active) {
            // S = Q K^T
            float sc[8][4];
#pragma unroll
            for (int tn = 0; tn < 8; tn++)
#pragma unroll
                for (int j = 0; j < 4; j++) sc[tn][j] = 0.0f;

#pragma unroll
            for (int k0 = 0; k0 < DKH; k0 += 8) {
                float2 qa = *(const float2*)&QSV(wid*16 + lg,     k0 + 2*lk);
                float2 qb = *(const float2*)&QSV(wid*16 + lg + 8, k0 + 2*lk);
                uint32_t a0 = f2tf(qa.x), a2 = f2tf(qa.y);
                uint32_t a1 = f2tf(qb.x), a3 = f2tf(qb.y);
#pragma unroll
                for (int tn = 0; tn < 8; tn++) {
                    float2 kv = *(const float2*)&KSV(s, tn*8 + lg, k0 + 2*lk);
                    mma_tf32(sc[tn], a0, a1, a2, a3, f2tf(kv.x), f2tf(kv.y));
                }
            }

            // scale + causal mask
#pragma unroll
            for (int tn = 0; tn < 8; tn++) {
                int c = kt*KT + tn*8 + 2*lk;
                sc[tn][0] = (c     > r0) ? -INFINITY : sc[tn][0]*scale;
                sc[tn][1] = (c + 1 > r0) ? -INFINITY : sc[tn][1]*scale;
                sc[tn][2] = (c     > r1) ? -INFINITY : sc[tn][2]*scale;
                sc[tn][3] = (c + 1 > r1) ? -INFINITY : sc[tn][3]*scale;
            }

            // online softmax (rows live in lane quads)
            float mx0 = -INFINITY, mx1 = -INFINITY;
#pragma unroll
            for (int tn = 0; tn < 8; tn++) {
                mx0 = fmaxf(mx0, fmaxf(sc[tn][0], sc[tn][1]));
                mx1 = fmaxf(mx1, fmaxf(sc[tn][2], sc[tn][3]));
            }
#pragma unroll
            for (int off = 1; off < 4; off <<= 1) {
                mx0 = fmaxf(mx0, __shfl_xor_sync(0xffffffffu, mx0, off));
                mx1 = fmaxf(mx1, __shfl_xor_sync(0xffffffffu, mx1, off));
            }
            float nm0 = fmaxf(m0, mx0), nm1 = fmaxf(m1, mx1);
            float al0 = __expf(m0 - nm0), al1 = __expf(m1 - nm1);
            float s0 = 0.0f, s1 = 0.0f;
#pragma unroll
            for (int tn = 0; tn < 8; tn++) {
                sc[tn][0] = __expf(sc[tn][0] - nm0); s0 += sc[tn][0];
                sc[tn][1] = __expf(sc[tn][1] - nm0); s0 += sc[tn][1];
                sc[tn][2] = __expf(sc[tn][2] - nm1); s1 += sc[tn][2];
                sc[tn][3] = __expf(sc[tn][3] - nm1); s1 += sc[tn][3];
            }
#pragma unroll
            for (int off = 1; off < 4; off <<= 1) {
                s0 += __shfl_xor_sync(0xffffffffu, s0, off);
                s1 += __shfl_xor_sync(0xffffffffu, s1, off);
            }
            l0 = l0*al0 + s0; l1 = l1*al1 + s1;
            m0 = nm0; m1 = nm1;
#pragma unroll
            for (int tn = 0; tn < 8; tn++) {
                o[tn][0] *= al0; o[tn][1] *= al0;
                o[tn][2] *= al1; o[tn][3] *= al1;
            }

            // P -> warp-private smem
#pragma unroll
            for (int tn = 0; tn < 8; tn++) {
                *(float2*)&PSV(wid*16 + lg,     tn*8 + 2*lk) = make_float2(sc[tn][0], sc[tn][1]);
                *(float2*)&PSV(wid*16 + lg + 8, tn*8 + 2*lk) = make_float2(sc[tn][2], sc[tn][3]);
            }
            __syncwarp();

            // O += P V
#pragma unroll
            for (int k0 = 0; k0 < KT; k0 += 8) {
                float2 pa = *(const float2*)&PSV(wid*16 + lg,     k0 + 2*lk);
                float2 pb = *(const float2*)&PSV(wid*16 + lg + 8, k0 + 2*lk);
                uint32_t a0 = f2tf(pa.x), a2 = f2tf(pa.y);
                uint32_t a1 = f2tf(pb.x), a3 = f2tf(pb.y);
#pragma unroll
                for (int tn = 0; tn < 8; tn++) {
                    uint32_t b0 = f2tf(VSV(s, k0 + 2*lk,     tn*8 + lg));
                    uint32_t b1 = f2tf(VSV(s, k0 + 2*lk + 1, tn*8 + lg));
                    mma_tf32(o[tn], a0, a1, a2, a3, b0, b1);
                }
            }
            __syncwarp();   // all lanes done reading P before next tile's store
        }
        __syncthreads();   // protect KV buffer reuse
    }

    // write normalized output into [B,S,H*dk]
    float inv0 = 1.0f / l0, inv1 = 1.0f / l1;
    float* base0 = AO + ((size_t)(b*SEQ + r0) * DM) + h*DKH;
    float* base1 = AO + ((size_t)(b*SEQ + r1) * DM) + h*DKH;
#pragma unroll
    for (int tn = 0; tn < 8; tn++) {
        int c = tn*8 + 2*lk;
        *(float2*)(base0 + c) = make_float2(o[tn][0]*inv0, o[tn][1]*inv0);
        *(float2*)(base1 + c) = make_float2(o[tn][2]*inv1, o[tn][3]*inv1);
    }
#undef LOAD_KV
#undef QSV
#undef KSV
#undef VSV
#undef PSV
}

// ---------------------------------------------------------------------------
extern "C" void kernel_launch(void* const* d_in, const int* in_sizes, int n_in,
                              void* d_out, int out_size)
{
    const float* x  = (const float*)d_in[0];
    const float* wq = (const float*)d_in[1];
    const float* wk = (const float*)d_in[2];
    const float* wv = (const float*)d_in[3];
    const float* wo = (const float*)d_in[4];

    float *Qp, *Kp, *Vp, *AOp;
    cudaGetSymbolAddress((void**)&Qp,  g_Q);
    cudaGetSymbolAddress((void**)&Kp,  g_K);
    cudaGetSymbolAddress((void**)&Vp,  g_V);
    cudaGetSymbolAddress((void**)&AOp, g_AO);

    static int attr_set = 0;
    if (!attr_set) {
        cudaFuncSetAttribute(mma_gemm, cudaFuncAttributeMaxDynamicSharedMemorySize, GSMEM_B);
        cudaFuncSetAttribute(attn_mma, cudaFuncAttributeMaxDynamicSharedMemorySize, ASMEM_B);
        attr_set = 1;
    }

    // QKV projections (tf32 mma.sync), scatter to [B,H,S,dk]
    dim3 g1(DM/128, MTOT/128, 3);
    mma_gemm<<<g1, 256, GSMEM_B>>>(x, wq, wk, wv, Qp, Kp, Vp, 1);

    // Causal attention (tf32 mma.sync)
    dim3 g2(SEQ/QT, BB*NH, 1);
    attn_mma<<<g2, 256, ASMEM_B>>>(Qp, Kp, Vp, AOp);

    // Output projection (tf32 mma.sync) -> d_out
    dim3 g3(DM/128, MTOT/128, 1);
    mma_gemm<<<g3, 256, GSMEM_B>>>(AOp, wo, wo, wo,
                                   (float*)d_out, (float*)d_out, (float*)d_out, 0);
}